// round 5
// baseline (speedup 1.0000x reference)
#include <cuda_runtime.h>

#define N_SAMPLES 32768
#define N_ITERS   16
#define KLEN      256
#define N_FRAMES  512
#define N_ATOMS   256
#define THREADS   1024
#define STEP      (N_SAMPLES / N_FRAMES)   // 64
#define N_VEC4    (N_SAMPLES / 4)          // 8192 float4s
#define ZERO_BLOCKS 8
#define GRID      (1 + ZERO_BLOCKS)

// dynamic smem (block 0 only actually uses it): full signal addressing range, 128 KB
extern __shared__ float sig[];

__device__ __forceinline__ void warp_argmax(const float* __restrict__ row, int n,
                                            int lane, float& bv, int& bi)
{
    bv = -3.402823466e38f;
    bi = 0x7fffffff;
    for (int c = lane; c < n; c += 32) {
        float v = row[c];
        if (v > bv) { bv = v; bi = c; }
    }
    #pragma unroll
    for (int o = 16; o > 0; o >>= 1) {
        float ov = __shfl_down_sync(0xffffffffu, bv, o);
        int   oi = __shfl_down_sync(0xffffffffu, bi, o);
        if (ov > bv || (ov == bv && oi < bi)) { bv = ov; bi = oi; }
    }
}

__global__ __launch_bounds__(THREADS, 1)
void Model_67817533604348_kernel(const float* __restrict__ atom_sel,   // [16,256]
                                 const float* __restrict__ amps,       // [16,1]
                                 const float* __restrict__ sched,      // [16,512]
                                 const float* __restrict__ d,          // [256,256]
                                 float* __restrict__ out)              // [32768]
{
    __shared__ int   s_aidx[N_ITERS];
    __shared__ int   s_pos[N_ITERS];
    __shared__ float s_red[32];
    __shared__ float s_scale;

    const int tid  = threadIdx.x;
    const int wid  = tid >> 5;
    const int lane = tid & 31;

    if (blockIdx.x != 0) {
        // ================= ZERO-WRITER BLOCKS =================
        // Recompute sched argmaxes (parallel, independent of block 0),
        // then write zeros to every non-window float4 of out.
        if (wid < N_ITERS) {
            float bv; int bi;
            warp_argmax(sched + wid * N_FRAMES, N_FRAMES, lane, bv, bi);
            if (lane == 0) s_pos[wid] = bi * STEP;
        }
        __syncthreads();

        const int v = (int)(blockIdx.x - 1) * THREADS + tid;   // float4 index [0,8192)
        bool covered = false;
        #pragma unroll
        for (int i = 0; i < N_ITERS; i++) {
            unsigned w4 = (unsigned)(s_pos[i] >> 2);           // window start in float4s
            covered |= ((unsigned)v - w4) < (unsigned)(KLEN / 4);
        }
        if (!covered)
            reinterpret_cast<float4*>(out)[v] = make_float4(0.f, 0.f, 0.f, 0.f);
        return;
    }

    // ================= COMPUTE BLOCK (block 0) =================
    // Phase 1: argmaxes — warps 0-15: atom_selection rows; warps 16-31: sched rows.
    // softmax is monotone -> argmax of raw logits; soft_dirac forward is exact one-hot.
    if (wid < N_ITERS) {
        float bv; int bi;
        warp_argmax(atom_sel + wid * N_ATOMS, N_ATOMS, lane, bv, bi);
        if (lane == 0) s_aidx[wid] = bi;
    } else {
        const int i = wid - N_ITERS;
        float bv; int bi;
        warp_argmax(sched + i * N_FRAMES, N_FRAMES, lane, bv, bi);
        if (lane == 0) s_pos[i] = bi * STEP;
    }
    __syncthreads();

    // Phase 2: gather amp-scaled atom taps; zero exactly the scatter targets.
    // Task: thread owns 4 consecutive taps of one iter. 64 threads per iter.
    const int it = tid >> 6;            // iter
    const int k0 = (tid & 63) << 2;     // first tap (multiple of 4)
    const float  amp = amps[it];
    const float4 dv  = *reinterpret_cast<const float4*>(d + s_aidx[it] * KLEN + k0);
    const int s0 = s_pos[it] + k0;      // 4-aligned (positions are multiples of 64)
    const bool ok = s0 < N_SAMPLES;     // truncated window tail dropped (aligned cut)

    if (ok)  // duplicate zero-writes on overlapping windows are idempotent
        *reinterpret_cast<float4*>(&sig[s0]) = make_float4(0.f, 0.f, 0.f, 0.f);
    __syncthreads();

    if (ok) {
        atomicAdd(&sig[s0 + 0], amp * dv.x);
        atomicAdd(&sig[s0 + 1], amp * dv.y);
        atomicAdd(&sig[s0 + 2], amp * dv.z);
        atomicAdd(&sig[s0 + 3], amp * dv.w);
    }
    __syncthreads();

    // Phase 3: max-abs over window samples only (non-window samples are exactly 0).
    float4 wv = make_float4(0.f, 0.f, 0.f, 0.f);
    float mx = 0.0f;
    if (ok) {
        wv = *reinterpret_cast<const float4*>(&sig[s0]);
        mx = fmaxf(fmaxf(fabsf(wv.x), fabsf(wv.y)), fmaxf(fabsf(wv.z), fabsf(wv.w)));
    }
    #pragma unroll
    for (int o = 16; o > 0; o >>= 1)
        mx = fmaxf(mx, __shfl_xor_sync(0xffffffffu, mx, o));
    if (lane == 0) s_red[wid] = mx;
    __syncthreads();
    if (wid == 0) {
        float m = s_red[lane];
        #pragma unroll
        for (int o = 16; o > 0; o >>= 1)
            m = fmaxf(m, __shfl_xor_sync(0xffffffffu, m, o));
        if (lane == 0) s_scale = 1.0f / (m + 1e-8f);
    }
    __syncthreads();

    // Phase 4: store only the window float4s (coalesced; duplicate stores on
    // overlapping windows carry bitwise-identical values — benign).
    const float scale = s_scale;
    if (ok) {
        wv.x *= scale; wv.y *= scale; wv.z *= scale; wv.w *= scale;
        *reinterpret_cast<float4*>(&out[s0]) = wv;
    }
}

extern "C" void kernel_launch(void* const* d_in, const int* in_sizes, int n_in,
                              void* d_out, int out_size) {
    // metadata order: x (unused), atom_selection, amps, sched_params, d
    const float* atom_sel = (const float*)d_in[1];
    const float* amps     = (const float*)d_in[2];
    const float* sched    = (const float*)d_in[3];
    const float* d        = (const float*)d_in[4];
    float* out            = (float*)d_out;

    const int smem = N_SAMPLES * (int)sizeof(float);  // 128 KB
    cudaFuncSetAttribute(Model_67817533604348_kernel,
                         cudaFuncAttributeMaxDynamicSharedMemorySize, smem);
    Model_67817533604348_kernel<<<GRID, THREADS, smem>>>(atom_sel, amps, sched, d, out);
}